// round 1
// baseline (speedup 1.0000x reference)
#include <cuda_runtime.h>
#include <math.h>

// Problem constants (fixed by setup_inputs)
#define BB    4
#define NTOK  6400
#define DM    256
#define HH    8
#define HD    32
#define PP    9
#define HIMG  40
#define WIMG  160
#define MROWS (BB * NTOK)   // 25600

// Scratch (device globals — no allocation allowed in kernel_launch)
__device__ float g_q[(size_t)MROWS * DM];              // 26.2 MB
__device__ float g_off[(size_t)MROWS * HH * PP * 2];   // 14.7 MB
__device__ float g_kv[(size_t)MROWS * 2 * DM];         // 52.4 MB
__device__ float g_att[(size_t)MROWS * DM];            // 26.2 MB

// ---------------------------------------------------------------------------
// C[M, Nc] = X[M, K] @ W[Nc, K]^T + bias   (fp32, 128x128x8 tiling, 8x8/thread)
// ---------------------------------------------------------------------------
__global__ __launch_bounds__(256)
void sgemm_bias_kernel(const float* __restrict__ X, const float* __restrict__ W,
                       const float* __restrict__ bias, float* __restrict__ C,
                       int M, int Nc, int K) {
    const int BM = 128, BN = 128, BK = 8;
    __shared__ float As[8][128];
    __shared__ float Bs[8][128];

    const int tid = threadIdx.x;
    const int tx = tid % 16;        // N-frag
    const int ty = tid / 16;        // M-frag
    const int m0 = blockIdx.y * BM;
    const int n0 = blockIdx.x * BN;

    float acc[8][8];
#pragma unroll
    for (int i = 0; i < 8; i++)
#pragma unroll
        for (int j = 0; j < 8; j++) acc[i][j] = 0.f;

    for (int k0 = 0; k0 < K; k0 += BK) {
#pragma unroll
        for (int i = 0; i < (BM * BK) / 256; i++) {
            int idx = tid + i * 256;
            int r = idx / BK, c = idx % BK;
            int gm = m0 + r;
            As[c][r] = (gm < M) ? X[(size_t)gm * K + k0 + c] : 0.f;
        }
#pragma unroll
        for (int i = 0; i < (BN * BK) / 256; i++) {
            int idx = tid + i * 256;
            int r = idx / BK, c = idx % BK;
            int gn = n0 + r;
            Bs[c][r] = (gn < Nc) ? W[(size_t)gn * K + k0 + c] : 0.f;
        }
        __syncthreads();
#pragma unroll
        for (int kk = 0; kk < BK; kk++) {
            float a[8], b[8];
#pragma unroll
            for (int i = 0; i < 8; i++) a[i] = As[kk][ty * 8 + i];
#pragma unroll
            for (int j = 0; j < 8; j++) b[j] = Bs[kk][tx * 8 + j];
#pragma unroll
            for (int i = 0; i < 8; i++)
#pragma unroll
                for (int j = 0; j < 8; j++)
                    acc[i][j] = fmaf(a[i], b[j], acc[i][j]);
        }
        __syncthreads();
    }

#pragma unroll
    for (int i = 0; i < 8; i++) {
        int gm = m0 + ty * 8 + i;
        if (gm >= M) continue;
#pragma unroll
        for (int j = 0; j < 8; j++) {
            int gn = n0 + tx * 8 + j;
            if (gn < Nc) C[(size_t)gm * Nc + gn] = acc[i][j] + bias[gn];
        }
    }
}

// ---------------------------------------------------------------------------
// Deformable attention core: one warp per (b, h, n). lane = channel (hd=32).
// Bilinear-gathers k,v from the interleaved kv buffer, warp-dot for logits,
// P=9 softmax in registers, weighted v-sum -> g_att.
// ---------------------------------------------------------------------------
__global__ __launch_bounds__(256)
void deform_attn_kernel(const float* __restrict__ q,
                        const float* __restrict__ off,
                        const float* __restrict__ kv,
                        float* __restrict__ out) {
    const int token = blockIdx.x;          // 0 .. B*N-1
    const int b = token / NTOK;
    const int n = token - b * NTOK;
    const int h = threadIdx.x >> 5;        // warp = head
    const int lane = threadIdx.x & 31;     // channel

    const float xbase = (float)(n % WIMG);
    const float ybase = (float)(n / WIMG);

    const float qc = q[(size_t)token * DM + h * HD + lane];
    const float* offrow = off + (size_t)token * (HH * PP * 2) + h * PP * 2;
    const float* kvb = kv + (size_t)b * NTOK * (2 * DM) + h * HD + lane;

    const float scale = rsqrtf((float)HD);
    float logits[PP], vs[PP];

#pragma unroll
    for (int p = 0; p < PP; p++) {
        float sx = xbase + tanhf(offrow[2 * p + 0]) * 4.0f;
        float sy = ybase + tanhf(offrow[2 * p + 1]) * 4.0f;
        float x0f = floorf(sx), y0f = floorf(sy);
        int x0 = (int)x0f, y0 = (int)y0f;
        float wx1 = sx - x0f, wx0 = 1.f - wx1;
        float wy1 = sy - y0f, wy0 = 1.f - wy1;

        float kacc = 0.f, vacc = 0.f;
#pragma unroll
        for (int cy = 0; cy < 2; cy++) {
            int yy = y0 + cy;
            if (yy < 0 || yy > HIMG - 1) continue;
            float wy = cy ? wy1 : wy0;
#pragma unroll
            for (int cx = 0; cx < 2; cx++) {
                int xx = x0 + cx;
                if (xx < 0 || xx > WIMG - 1) continue;
                float wx = cx ? wx1 : wx0;
                float wgt = wx * wy;
                const float* row = kvb + (size_t)(yy * WIMG + xx) * (2 * DM);
                kacc = fmaf(wgt, row[0], kacc);
                vacc = fmaf(wgt, row[DM], vacc);
            }
        }
        float d = qc * kacc;
#pragma unroll
        for (int s = 16; s; s >>= 1) d += __shfl_xor_sync(0xffffffffu, d, s);
        logits[p] = d * scale;
        vs[p] = vacc;
    }

    float mx = logits[0];
#pragma unroll
    for (int p = 1; p < PP; p++) mx = fmaxf(mx, logits[p]);
    float sum = 0.f;
#pragma unroll
    for (int p = 0; p < PP; p++) { logits[p] = __expf(logits[p] - mx); sum += logits[p]; }
    float inv = 1.f / sum;
    float o = 0.f;
#pragma unroll
    for (int p = 0; p < PP; p++) o = fmaf(logits[p], vs[p], o);

    out[(size_t)token * DM + h * HD + lane] = o * inv;
}

// ---------------------------------------------------------------------------
extern "C" void kernel_launch(void* const* d_in, const int* in_sizes, int n_in,
                              void* d_out, int out_size) {
    const float* x    = (const float*)d_in[0];
    const float* Wq   = (const float*)d_in[1];
    const float* bq   = (const float*)d_in[2];
    const float* Woff = (const float*)d_in[3];
    const float* boff = (const float*)d_in[4];
    const float* Wkv  = (const float*)d_in[5];
    const float* bkv  = (const float*)d_in[6];
    const float* Wout = (const float*)d_in[7];
    const float* bout = (const float*)d_in[8];
    float* out = (float*)d_out;

    float *qp, *offp, *kvp, *attp;
    cudaGetSymbolAddress((void**)&qp, g_q);
    cudaGetSymbolAddress((void**)&offp, g_off);
    cudaGetSymbolAddress((void**)&kvp, g_kv);
    cudaGetSymbolAddress((void**)&attp, g_att);

    const int M = MROWS;
    dim3 blk(256);

    // q = x @ Wq^T + bq             (M x 256)
    sgemm_bias_kernel<<<dim3(2, (M + 127) / 128), blk>>>(x, Wq, bq, qp, M, 256, 256);
    // offsets (pre-tanh) = x @ Woff^T + boff   (M x 144)
    sgemm_bias_kernel<<<dim3(2, (M + 127) / 128), blk>>>(x, Woff, boff, offp, M, 144, 256);
    // kv = x @ Wkv^T + bkv          (M x 512)
    sgemm_bias_kernel<<<dim3(4, (M + 127) / 128), blk>>>(x, Wkv, bkv, kvp, M, 512, 256);

    // deformable attention -> g_att (M x 256)
    deform_attn_kernel<<<M, 256>>>(qp, offp, kvp, attp);

    // out = g_att @ Wout^T + bout   (M x 256)
    sgemm_bias_kernel<<<dim3(2, (M + 127) / 128), blk>>>(attp, Wout, bout, out, M, 256, 256);
}

// round 2
// speedup vs baseline: 1.5159x; 1.5159x over previous
#include <cuda_runtime.h>
#include <math.h>

// Problem constants (fixed by setup_inputs)
#define BB    4
#define NTOK  6400
#define DM    256
#define HH    8
#define HD    32
#define PP    9
#define HIMG  40
#define WIMG  160
#define MROWS (BB * NTOK)   // 25600

// Scratch (device globals — no allocation allowed in kernel_launch)
__device__ float g_q[(size_t)MROWS * DM];              // 26.2 MB
__device__ float g_off[(size_t)MROWS * HH * PP * 2];   // 14.7 MB (stores tanh(..)*4 final offsets)
__device__ float g_kv[(size_t)MROWS * 2 * DM];         // 52.4 MB
__device__ float g_att[(size_t)MROWS * DM];            // 26.2 MB

// ---------------------------------------------------------------------------
// SGEMM body: C[m0:m0+128, n0:n0+128] = X[m0:,:256] @ W[n0:,:256]^T + bias
// K fixed at 256. 128x128x16 tile, 8x8 per thread, float4 loads.
// M assumed multiple of 128 (25600 = 200*128). Nc guarded.
// ---------------------------------------------------------------------------
__device__ __forceinline__ void sgemm_body(
    const float* __restrict__ X, const float* __restrict__ W,
    const float* __restrict__ bias, float* __restrict__ C,
    int Nc, int ldC, int m0, int n0, bool tanh_ep)
{
    __shared__ float As[16][128];
    __shared__ float Bs[16][128];

    const int tid = threadIdx.x;
    const int tx = tid & 15;      // N-frag
    const int ty = tid >> 4;      // M-frag

    float acc[8][8];
#pragma unroll
    for (int i = 0; i < 8; i++)
#pragma unroll
        for (int j = 0; j < 8; j++) acc[i][j] = 0.f;

#pragma unroll 1
    for (int k0 = 0; k0 < 256; k0 += 16) {
#pragma unroll
        for (int i = 0; i < 2; i++) {
            int f = tid + i * 256;
            int r = f >> 2;
            int c = (f & 3) * 4;
            float4 av = *(const float4*)(X + (size_t)(m0 + r) * 256 + k0 + c);
            As[c + 0][r] = av.x; As[c + 1][r] = av.y;
            As[c + 2][r] = av.z; As[c + 3][r] = av.w;

            int gn = n0 + r;
            float4 bv = make_float4(0.f, 0.f, 0.f, 0.f);
            if (gn < Nc)
                bv = *(const float4*)(W + (size_t)gn * 256 + k0 + c);
            Bs[c + 0][r] = bv.x; Bs[c + 1][r] = bv.y;
            Bs[c + 2][r] = bv.z; Bs[c + 3][r] = bv.w;
        }
        __syncthreads();

#pragma unroll
        for (int kk = 0; kk < 16; kk++) {
            float4 a0 = *(const float4*)&As[kk][ty * 8];
            float4 a1 = *(const float4*)&As[kk][ty * 8 + 4];
            float4 b0 = *(const float4*)&Bs[kk][tx * 8];
            float4 b1 = *(const float4*)&Bs[kk][tx * 8 + 4];
            float a[8] = {a0.x, a0.y, a0.z, a0.w, a1.x, a1.y, a1.z, a1.w};
            float b[8] = {b0.x, b0.y, b0.z, b0.w, b1.x, b1.y, b1.z, b1.w};
#pragma unroll
            for (int i = 0; i < 8; i++)
#pragma unroll
                for (int j = 0; j < 8; j++)
                    acc[i][j] = fmaf(a[i], b[j], acc[i][j]);
        }
        __syncthreads();
    }

    // Epilogue
#pragma unroll
    for (int i = 0; i < 8; i++) {
        int gm = m0 + ty * 8 + i;
        float* crow = C + (size_t)gm * ldC;
#pragma unroll
        for (int j = 0; j < 8; j++) {
            int gn = n0 + tx * 8 + j;
            if (gn < Nc) {
                float v = acc[i][j] + bias[gn];
                if (tanh_ep) v = tanhf(v) * 4.0f;
                crow[gn] = v;
            }
        }
    }
}

// Fused input GEMMs: blockIdx.x tiles 0-1 -> q, 2-3 -> off(tanh*4), 4-7 -> kv
__global__ __launch_bounds__(256)
void fused_in_gemm(const float* __restrict__ X,
                   const float* __restrict__ Wq,  const float* __restrict__ bq,
                   const float* __restrict__ Wo,  const float* __restrict__ bo,
                   const float* __restrict__ Wkv, const float* __restrict__ bkv,
                   float* __restrict__ Cq, float* __restrict__ Co, float* __restrict__ Ckv)
{
    const int t = blockIdx.x;
    const int m0 = blockIdx.y * 128;
    if (t < 2)      sgemm_body(X, Wq,  bq,  Cq,  256, 256, m0, t * 128,       false);
    else if (t < 4) sgemm_body(X, Wo,  bo,  Co,  144, 144, m0, (t - 2) * 128, true);
    else            sgemm_body(X, Wkv, bkv, Ckv, 512, 512, m0, (t - 4) * 128, false);
}

__global__ __launch_bounds__(256)
void out_gemm(const float* __restrict__ X, const float* __restrict__ W,
              const float* __restrict__ bias, float* __restrict__ C)
{
    sgemm_body(X, W, bias, C, 256, 256, blockIdx.y * 128, blockIdx.x * 128, false);
}

// ---------------------------------------------------------------------------
// Deformable attention core: one warp per (b, h, n). lane = channel (hd=32).
// Offsets already tanh'd*4. Interior fast path with immediate corner offsets.
// ---------------------------------------------------------------------------
__global__ __launch_bounds__(256)
void deform_attn_kernel(const float* __restrict__ q,
                        const float* __restrict__ off,
                        const float* __restrict__ kv,
                        float* __restrict__ out)
{
    const int token = blockIdx.x;
    const int b = token / NTOK;
    const int n = token - b * NTOK;
    const int h = threadIdx.x >> 5;
    const int lane = threadIdx.x & 31;

    const float xbase = (float)(n % WIMG);
    const float ybase = (float)(n / WIMG);

    const float qc = q[(size_t)token * DM + h * HD + lane];
    const float2* offp = (const float2*)(off + (size_t)token * (HH * PP * 2) + h * PP * 2);
    const float* kvb = kv + (size_t)b * NTOK * (2 * DM) + h * HD + lane;

    float logits[PP], vs[PP];

#pragma unroll
    for (int p = 0; p < PP; p++) {
        float2 o = __ldg(&offp[p]);
        float sx = xbase + o.x;
        float sy = ybase + o.y;
        float x0f = floorf(sx), y0f = floorf(sy);
        int x0 = (int)x0f, y0 = (int)y0f;
        float wx1 = sx - x0f, wx0 = 1.f - wx1;
        float wy1 = sy - y0f, wy0 = 1.f - wy1;

        float kacc, vacc;
        if ((unsigned)x0 < (unsigned)(WIMG - 1) && (unsigned)y0 < (unsigned)(HIMG - 1)) {
            // interior: all 4 corners valid, constant corner offsets
            const float* p00 = kvb + (size_t)(y0 * WIMG + x0) * (2 * DM);
            float w00 = wx0 * wy0, w10 = wx1 * wy0;
            float w01 = wx0 * wy1, w11 = wx1 * wy1;
            kacc = w00 * p00[0]
                 + w10 * p00[2 * DM]
                 + w01 * p00[WIMG * 2 * DM]
                 + w11 * p00[(WIMG + 1) * 2 * DM];
            vacc = w00 * p00[DM]
                 + w10 * p00[2 * DM + DM]
                 + w01 * p00[WIMG * 2 * DM + DM]
                 + w11 * p00[(WIMG + 1) * 2 * DM + DM];
        } else {
            kacc = 0.f; vacc = 0.f;
#pragma unroll
            for (int cy = 0; cy < 2; cy++) {
                int yy = y0 + cy;
                if ((unsigned)yy >= (unsigned)HIMG) continue;
                float wy = cy ? wy1 : wy0;
#pragma unroll
                for (int cx = 0; cx < 2; cx++) {
                    int xx = x0 + cx;
                    if ((unsigned)xx >= (unsigned)WIMG) continue;
                    float wgt = (cx ? wx1 : wx0) * wy;
                    const float* row = kvb + (size_t)(yy * WIMG + xx) * (2 * DM);
                    kacc = fmaf(wgt, row[0], kacc);
                    vacc = fmaf(wgt, row[DM], vacc);
                }
            }
        }
        float d = qc * kacc;
#pragma unroll
        for (int s = 16; s; s >>= 1) d += __shfl_xor_sync(0xffffffffu, d, s);
        logits[p] = d;
        vs[p] = vacc;
    }

    const float scale = rsqrtf((float)HD);
    float mx = logits[0] * scale;
#pragma unroll
    for (int p = 0; p < PP; p++) { logits[p] *= scale; mx = fmaxf(mx, logits[p]); }
    float sum = 0.f;
#pragma unroll
    for (int p = 0; p < PP; p++) { logits[p] = __expf(logits[p] - mx); sum += logits[p]; }
    float inv = 1.f / sum;
    float o = 0.f;
#pragma unroll
    for (int p = 0; p < PP; p++) o = fmaf(logits[p], vs[p], o);

    out[(size_t)token * DM + h * HD + lane] = o * inv;
}

// ---------------------------------------------------------------------------
extern "C" void kernel_launch(void* const* d_in, const int* in_sizes, int n_in,
                              void* d_out, int out_size) {
    const float* x    = (const float*)d_in[0];
    const float* Wq   = (const float*)d_in[1];
    const float* bq   = (const float*)d_in[2];
    const float* Woff = (const float*)d_in[3];
    const float* boff = (const float*)d_in[4];
    const float* Wkv  = (const float*)d_in[5];
    const float* bkv  = (const float*)d_in[6];
    const float* Wout = (const float*)d_in[7];
    const float* bout = (const float*)d_in[8];
    float* out = (float*)d_out;

    float *qp, *offp, *kvp, *attp;
    cudaGetSymbolAddress((void**)&qp, g_q);
    cudaGetSymbolAddress((void**)&offp, g_off);
    cudaGetSymbolAddress((void**)&kvp, g_kv);
    cudaGetSymbolAddress((void**)&attp, g_att);

    dim3 blk(256);

    // q | tanh(off)*4 | kv  (fused, 8 column tiles x 200 row tiles)
    fused_in_gemm<<<dim3(8, MROWS / 128), blk>>>(x, Wq, bq, Woff, boff, Wkv, bkv,
                                                 qp, offp, kvp);

    // deformable attention -> g_att (M x 256)
    deform_attn_kernel<<<MROWS, 256>>>(qp, offp, kvp, attp);

    // out = g_att @ Wout^T + bout   (M x 256)
    out_gemm<<<dim3(2, MROWS / 128), blk>>>(attp, Wout, bout, out);
}

// round 4
// speedup vs baseline: 2.4131x; 1.5918x over previous
#include <cuda_runtime.h>
#include <cuda_bf16.h>
#include <math.h>
#include <stdint.h>

// Problem constants (fixed by setup_inputs)
#define BB    4
#define NTOK  6400
#define DM    256
#define HH    8
#define HD    32
#define PP    9
#define HIMG  40
#define WIMG  160
#define MROWS (BB * NTOK)   // 25600
#define KK    256

// ---------------- scratch (device globals; no allocation allowed) ----------
__device__ float   g_q  [(size_t)MROWS * DM];
__device__ float   g_off[(size_t)MROWS * HH * PP * 2];   // tanh(..)*4 final offsets
__device__ float   g_kv [(size_t)MROWS * 2 * DM];

__device__ __align__(16) uint16_t g_xhi[(size_t)MROWS * KK];
__device__ __align__(16) uint16_t g_xlo[(size_t)MROWS * KK];
__device__ __align__(16) uint16_t g_ahi[(size_t)MROWS * DM];
__device__ __align__(16) uint16_t g_alo[(size_t)MROWS * DM];

__device__ __align__(16) uint16_t g_wq_hi [256 * KK],  g_wq_lo [256 * KK];
__device__ __align__(16) uint16_t g_wo_hi [144 * KK],  g_wo_lo [144 * KK];
__device__ __align__(16) uint16_t g_wkv_hi[512 * KK],  g_wkv_lo[512 * KK];
__device__ __align__(16) uint16_t g_wu_hi [256 * KK],  g_wu_lo [256 * KK];

// ---------------- warp MMA helpers (base-ISA: ldmatrix + mma.sync) ---------
__device__ __forceinline__ uint32_t smem_u32(const void* p) {
    uint32_t a;
    asm("{ .reg .u64 t; cvta.to.shared.u64 t, %1; cvt.u32.u64 %0, t; }" : "=r"(a) : "l"(p));
    return a;
}

__device__ __forceinline__ void ldsm_x4(uint32_t* r, uint32_t addr) {
    asm volatile("ldmatrix.sync.aligned.m8n8.x4.shared.b16 {%0,%1,%2,%3}, [%4];"
        : "=r"(r[0]), "=r"(r[1]), "=r"(r[2]), "=r"(r[3]) : "r"(addr));
}
__device__ __forceinline__ void ldsm_x2(uint32_t* r, uint32_t addr) {
    asm volatile("ldmatrix.sync.aligned.m8n8.x2.shared.b16 {%0,%1}, [%2];"
        : "=r"(r[0]), "=r"(r[1]) : "r"(addr));
}
__device__ __forceinline__ void mma16816(float* c, const uint32_t* a, const uint32_t* b) {
    asm volatile("mma.sync.aligned.m16n8k16.row.col.f32.bf16.bf16.f32 "
        "{%0,%1,%2,%3}, {%4,%5,%6,%7}, {%8,%9}, {%0,%1,%2,%3};"
        : "+f"(c[0]), "+f"(c[1]), "+f"(c[2]), "+f"(c[3])
        : "r"(a[0]), "r"(a[1]), "r"(a[2]), "r"(a[3]), "r"(b[0]), "r"(b[1]));
}

// SMEM layout (dynamic): A hi/lo [128][72], B hi/lo [64][72] bf16
#define LDS  72
#define OFF_AH 0
#define OFF_AL (128 * LDS)
#define OFF_BH (2 * 128 * LDS)
#define OFF_BL (2 * 128 * LDS + 64 * LDS)
#define SM_ELEMS (2 * 128 * LDS + 2 * 64 * LDS)      // 27648 elems
#define SM_BYTES (SM_ELEMS * 2)                      // 55296 B

// ---------------------------------------------------------------------------
// C[m0:m0+128, n0:n0+64] = A[m0:,:256] @ W[n0:,:256]^T + bias  (split-bf16)
// 256 threads, 8 warps as 4(M) x 2(N); warp tile 32x32.
// ---------------------------------------------------------------------------
__device__ __forceinline__ void gemm_tile_mma(
    const uint16_t* __restrict__ Ah, const uint16_t* __restrict__ Al,
    const uint16_t* __restrict__ Wh, const uint16_t* __restrict__ Wl,
    const float* __restrict__ bias, float* __restrict__ C,
    int Nc, int ldC, int m0, int n0, bool tanh_ep)
{
    extern __shared__ uint16_t sm[];
    const int tid = threadIdx.x;
    const int wid = tid >> 5, lane = tid & 31;
    const int wm = (wid & 3) * 32;
    const int wn = (wid >> 2) * 32;

    float acc[2][4][4];
#pragma unroll
    for (int mt = 0; mt < 2; mt++)
#pragma unroll
        for (int nt = 0; nt < 4; nt++)
#pragma unroll
            for (int i = 0; i < 4; i++) acc[mt][nt][i] = 0.f;

    // precompute ldmatrix lane addressing pieces
    const int a_r = lane & 15;          // row within 16
    const int a_c = (lane >> 4) * 8;    // 0 or 8 elements (16B)
    const int b_r = lane & 7;
    const int b_c = ((lane >> 3) & 1) * 8;

#pragma unroll 1
    for (int k0 = 0; k0 < 256; k0 += 64) {
        // ---- load A 128x64 hi+lo (uint4 = 8 elems; 1024 chunks, 4/thread)
#pragma unroll
        for (int i = 0; i < 4; i++) {
            int idx = tid + i * 256;
            int row = idx >> 3;
            int kc  = (idx & 7) * 8;
            size_t g = (size_t)(m0 + row) * KK + k0 + kc;
            *(uint4*)(sm + OFF_AH + row * LDS + kc) = *(const uint4*)(Ah + g);
            *(uint4*)(sm + OFF_AL + row * LDS + kc) = *(const uint4*)(Al + g);
        }
        // ---- load B 64x64 hi+lo (512 chunks, 2/thread), guard Nc
#pragma unroll
        for (int i = 0; i < 2; i++) {
            int idx = tid + i * 256;
            int row = idx >> 3;
            int kc  = (idx & 7) * 8;
            uint4 vh = make_uint4(0, 0, 0, 0), vl = vh;
            if (n0 + row < Nc) {
                size_t g = (size_t)(n0 + row) * KK + k0 + kc;
                vh = *(const uint4*)(Wh + g);
                vl = *(const uint4*)(Wl + g);
            }
            *(uint4*)(sm + OFF_BH + row * LDS + kc) = vh;
            *(uint4*)(sm + OFF_BL + row * LDS + kc) = vl;
        }
        __syncthreads();

#pragma unroll
        for (int ks = 0; ks < 4; ks++) {
            const int kb = ks * 16;
            uint32_t ah[2][4], al[2][4];
#pragma unroll
            for (int mt = 0; mt < 2; mt++) {
                int row = wm + mt * 16 + a_r;
                uint32_t ad_h = smem_u32(sm + OFF_AH + row * LDS + kb + a_c);
                uint32_t ad_l = smem_u32(sm + OFF_AL + row * LDS + kb + a_c);
                ldsm_x4(ah[mt], ad_h);
                ldsm_x4(al[mt], ad_l);
            }
            uint32_t bh[4][2], bl[4][2];
#pragma unroll
            for (int nt = 0; nt < 4; nt++) {
                int row = wn + nt * 8 + b_r;
                uint32_t bd_h = smem_u32(sm + OFF_BH + row * LDS + kb + b_c);
                uint32_t bd_l = smem_u32(sm + OFF_BL + row * LDS + kb + b_c);
                ldsm_x2(bh[nt], bd_h);
                ldsm_x2(bl[nt], bd_l);
            }
#pragma unroll
            for (int mt = 0; mt < 2; mt++)
#pragma unroll
                for (int nt = 0; nt < 4; nt++) {
                    mma16816(acc[mt][nt], ah[mt], bh[nt]);
                    mma16816(acc[mt][nt], ah[mt], bl[nt]);
                    mma16816(acc[mt][nt], al[mt], bh[nt]);
                }
        }
        __syncthreads();
    }

    // ---- epilogue: thread owns rows (t/4, t/4+8) cols (t%4)*2..+1 per tile
    const int er = lane >> 2;
    const int ec = (lane & 3) * 2;
#pragma unroll
    for (int mt = 0; mt < 2; mt++) {
#pragma unroll
        for (int half = 0; half < 2; half++) {
            int gm = m0 + wm + mt * 16 + er + half * 8;
            float* crow = C + (size_t)gm * ldC;
#pragma unroll
            for (int nt = 0; nt < 4; nt++) {
                int gn = n0 + wn + nt * 8 + ec;
                if (gn < Nc) {
                    float v0 = acc[mt][nt][half * 2 + 0] + bias[gn];
                    float v1 = acc[mt][nt][half * 2 + 1] + bias[gn + 1];
                    if (tanh_ep) { v0 = tanhf(v0) * 4.f; v1 = tanhf(v1) * 4.f; }
                    crow[gn]     = v0;
                    crow[gn + 1] = v1;
                }
            }
        }
    }
}

// in_gemm: blockIdx.x: 0-3 q | 4-6 off(tanh) | 7-14 kv
__global__ __launch_bounds__(256)
void in_gemm_mma(const float* __restrict__ bq, const float* __restrict__ bo,
                 const float* __restrict__ bkv)
{
    const int t = blockIdx.x;
    const int m0 = blockIdx.y * 128;
    if (t < 4)
        gemm_tile_mma(g_xhi, g_xlo, g_wq_hi, g_wq_lo, bq, g_q, 256, 256, m0, t * 64, false);
    else if (t < 7)
        gemm_tile_mma(g_xhi, g_xlo, g_wo_hi, g_wo_lo, bo, g_off, 144, 144, m0, (t - 4) * 64, true);
    else
        gemm_tile_mma(g_xhi, g_xlo, g_wkv_hi, g_wkv_lo, bkv, g_kv, 512, 512, m0, (t - 7) * 64, false);
}

__global__ __launch_bounds__(256)
void out_gemm_mma(const float* __restrict__ bout, float* __restrict__ C)
{
    gemm_tile_mma(g_ahi, g_alo, g_wu_hi, g_wu_lo, bout, C, 256, 256,
                  blockIdx.y * 128, blockIdx.x * 64, false);
}

// ---------------------------------------------------------------------------
// fp32 -> bf16 hi/lo splits
// ---------------------------------------------------------------------------
__device__ __forceinline__ void split1(float v, uint16_t& h, uint16_t& l) {
    __nv_bfloat16 hb = __float2bfloat16(v);
    __nv_bfloat16 lb = __float2bfloat16(v - __bfloat162float(hb));
    h = __bfloat16_as_ushort(hb);
    l = __bfloat16_as_ushort(lb);
}

__global__ __launch_bounds__(256)
void split_x_kernel(const float* __restrict__ x) {
    int i4 = blockIdx.x * 256 + threadIdx.x;            // 16B chunk id
    float4 v = ((const float4*)x)[i4];
    uint16_t h[4], l[4];
    split1(v.x, h[0], l[0]); split1(v.y, h[1], l[1]);
    split1(v.z, h[2], l[2]); split1(v.w, h[3], l[3]);
    ((uint64_t*)g_xhi)[i4] = *(const uint64_t*)h;
    ((uint64_t*)g_xlo)[i4] = *(const uint64_t*)l;
}

__global__ __launch_bounds__(256)
void split_w_kernel(const float* __restrict__ Wq, const float* __restrict__ Wo,
                    const float* __restrict__ Wkv, const float* __restrict__ Wu)
{
    int i = blockIdx.x * 256 + threadIdx.x;
    const float* src; uint16_t *hi, *lo; int off;
    if (i < 65536)        { src = Wq;  hi = g_wq_hi;  lo = g_wq_lo;  off = i; }
    else if (i < 102400)  { src = Wo;  hi = g_wo_hi;  lo = g_wo_lo;  off = i - 65536; }
    else if (i < 233472)  { src = Wkv; hi = g_wkv_hi; lo = g_wkv_lo; off = i - 102400; }
    else                  { src = Wu;  hi = g_wu_hi;  lo = g_wu_lo;  off = i - 233472; }
    split1(src[off], hi[off], lo[off]);
}

// ---------------------------------------------------------------------------
// Deformable attention: one warp per (b, h, n); lane = channel. Outputs bf16 hi/lo.
// ---------------------------------------------------------------------------
__global__ __launch_bounds__(256)
void deform_attn_kernel()
{
    const int token = blockIdx.x;
    const int b = token / NTOK;
    const int n = token - b * NTOK;
    const int h = threadIdx.x >> 5;
    const int lane = threadIdx.x & 31;

    const float xbase = (float)(n % WIMG);
    const float ybase = (float)(n / WIMG);

    const float qc = g_q[(size_t)token * DM + h * HD + lane];
    const float2* offp = (const float2*)(g_off + (size_t)token * (HH * PP * 2) + h * PP * 2);
    const float* kvb = g_kv + (size_t)b * NTOK * (2 * DM) + h * HD + lane;

    float logits[PP], vs[PP];

#pragma unroll
    for (int p = 0; p < PP; p++) {
        float2 o = __ldg(&offp[p]);
        float sx = xbase + o.x;
        float sy = ybase + o.y;
        float x0f = floorf(sx), y0f = floorf(sy);
        int x0 = (int)x0f, y0 = (int)y0f;
        float wx1 = sx - x0f, wx0 = 1.f - wx1;
        float wy1 = sy - y0f, wy0 = 1.f - wy1;

        float kacc, vacc;
        if ((unsigned)x0 < (unsigned)(WIMG - 1) && (unsigned)y0 < (unsigned)(HIMG - 1)) {
            const float* p00 = kvb + (size_t)(y0 * WIMG + x0) * (2 * DM);
            float w00 = wx0 * wy0, w10 = wx1 * wy0;
            float w01 = wx0 * wy1, w11 = wx1 * wy1;
            kacc = w00 * p00[0]
                 + w10 * p00[2 * DM]
                 + w01 * p00[WIMG * 2 * DM]
                 + w11 * p00[(WIMG + 1) * 2 * DM];
            vacc = w00 * p00[DM]
                 + w10 * p00[2 * DM + DM]
                 + w01 * p00[WIMG * 2 * DM + DM]
                 + w11 * p00[(WIMG + 1) * 2 * DM + DM];
        } else {
            kacc = 0.f; vacc = 0.f;
#pragma unroll
            for (int cy = 0; cy < 2; cy++) {
                int yy = y0 + cy;
                if ((unsigned)yy >= (unsigned)HIMG) continue;
                float wy = cy ? wy1 : wy0;
#pragma unroll
                for (int cx = 0; cx < 2; cx++) {
                    int xx = x0 + cx;
                    if ((unsigned)xx >= (unsigned)WIMG) continue;
                    float wgt = (cx ? wx1 : wx0) * wy;
                    const float* row = kvb + (size_t)(yy * WIMG + xx) * (2 * DM);
                    kacc = fmaf(wgt, row[0], kacc);
                    vacc = fmaf(wgt, row[DM], vacc);
                }
            }
        }
        float d = qc * kacc;
#pragma unroll
        for (int s = 16; s; s >>= 1) d += __shfl_xor_sync(0xffffffffu, d, s);
        logits[p] = d;
        vs[p] = vacc;
    }

    const float scale = 0.17677669529663687f;   // 1/sqrt(32)
    float mx = logits[0] * scale;
#pragma unroll
    for (int p = 0; p < PP; p++) { logits[p] *= scale; mx = fmaxf(mx, logits[p]); }
    float sum = 0.f;
#pragma unroll
    for (int p = 0; p < PP; p++) { logits[p] = __expf(logits[p] - mx); sum += logits[p]; }
    float inv = 1.f / sum;
    float o = 0.f;
#pragma unroll
    for (int p = 0; p < PP; p++) o = fmaf(logits[p], vs[p], o);
    o *= inv;

    uint16_t hh, ll;
    split1(o, hh, ll);
    size_t oi = (size_t)token * DM + h * HD + lane;
    g_ahi[oi] = hh;
    g_alo[oi] = ll;
}

// ---------------------------------------------------------------------------
extern "C" void kernel_launch(void* const* d_in, const int* in_sizes, int n_in,
                              void* d_out, int out_size) {
    const float* x    = (const float*)d_in[0];
    const float* Wq   = (const float*)d_in[1];
    const float* bq   = (const float*)d_in[2];
    const float* Woff = (const float*)d_in[3];
    const float* boff = (const float*)d_in[4];
    const float* Wkv  = (const float*)d_in[5];
    const float* bkv  = (const float*)d_in[6];
    const float* Wout = (const float*)d_in[7];
    const float* bout = (const float*)d_in[8];
    float* out = (float*)d_out;

    static bool attr_done = false;
    if (!attr_done) {
        cudaFuncSetAttribute(in_gemm_mma,  cudaFuncAttributeMaxDynamicSharedMemorySize, SM_BYTES);
        cudaFuncSetAttribute(out_gemm_mma, cudaFuncAttributeMaxDynamicSharedMemorySize, SM_BYTES);
        attr_done = true;
    }

    // fp32 -> bf16 hi/lo splits
    split_x_kernel<<<(MROWS * KK / 4) / 256, 256>>>(x);
    split_w_kernel<<<299008 / 256, 256>>>(Wq, Woff, Wkv, Wout);

    // q | tanh(off)*4 | kv  via mma.sync split-bf16
    in_gemm_mma<<<dim3(15, MROWS / 128), 256, SM_BYTES>>>(bq, boff, bkv);

    // deformable attention -> att hi/lo
    deform_attn_kernel<<<MROWS, 256>>>();

    // out = att @ Wout^T + bout
    out_gemm_mma<<<dim3(4, MROWS / 128), 256, SM_BYTES>>>(bout, out);
}

// round 5
// speedup vs baseline: 3.0357x; 1.2580x over previous
#include <cuda_runtime.h>
#include <cuda_bf16.h>
#include <math.h>
#include <stdint.h>

// Problem constants (fixed by setup_inputs)
#define BB    4
#define NTOK  6400
#define DM    256
#define HH    8
#define HD    32
#define PP    9
#define HIMG  40
#define WIMG  160
#define MROWS (BB * NTOK)   // 25600
#define KK    256

// ---------------- scratch (device globals; no allocation allowed) ----------
__device__ float   g_q  [(size_t)MROWS * DM];
__device__ float   g_off[(size_t)MROWS * HH * PP * 2];   // tanh(..)*4 final offsets
__device__ float   g_kv [(size_t)MROWS * 2 * DM];        // INTERLEAVED: [tok][ch][k,v]

__device__ __align__(16) uint16_t g_xhi[(size_t)MROWS * KK];
__device__ __align__(16) uint16_t g_xlo[(size_t)MROWS * KK];
__device__ __align__(16) uint16_t g_ahi[(size_t)MROWS * DM];
__device__ __align__(16) uint16_t g_alo[(size_t)MROWS * DM];

__device__ __align__(16) uint16_t g_wq_hi [256 * KK],  g_wq_lo [256 * KK];
__device__ __align__(16) uint16_t g_wo_hi [144 * KK],  g_wo_lo [144 * KK];
__device__ __align__(16) uint16_t g_wkv_hi[512 * KK],  g_wkv_lo[512 * KK];
__device__ __align__(16) uint16_t g_wu_hi [256 * KK],  g_wu_lo [256 * KK];

// ---------------- warp MMA helpers (base-ISA) ------------------------------
__device__ __forceinline__ uint32_t smem_u32(const void* p) {
    uint32_t a;
    asm("{ .reg .u64 t; cvta.to.shared.u64 t, %1; cvt.u32.u64 %0, t; }" : "=r"(a) : "l"(p));
    return a;
}
__device__ __forceinline__ void ldsm_x4(uint32_t* r, uint32_t addr) {
    asm volatile("ldmatrix.sync.aligned.m8n8.x4.shared.b16 {%0,%1,%2,%3}, [%4];"
        : "=r"(r[0]), "=r"(r[1]), "=r"(r[2]), "=r"(r[3]) : "r"(addr));
}
__device__ __forceinline__ void ldsm_x2(uint32_t* r, uint32_t addr) {
    asm volatile("ldmatrix.sync.aligned.m8n8.x2.shared.b16 {%0,%1}, [%2];"
        : "=r"(r[0]), "=r"(r[1]) : "r"(addr));
}
__device__ __forceinline__ void mma16816(float* c, const uint32_t* a, const uint32_t* b) {
    asm volatile("mma.sync.aligned.m16n8k16.row.col.f32.bf16.bf16.f32 "
        "{%0,%1,%2,%3}, {%4,%5,%6,%7}, {%8,%9}, {%0,%1,%2,%3};"
        : "+f"(c[0]), "+f"(c[1]), "+f"(c[2]), "+f"(c[3])
        : "r"(a[0]), "r"(a[1]), "r"(a[2]), "r"(a[3]), "r"(b[0]), "r"(b[1]));
}
#define CP_ASYNC16(dst, src) asm volatile("cp.async.cg.shared.global [%0], [%1], 16;" :: "r"(dst), "l"(src))
#define CP_COMMIT()          asm volatile("cp.async.commit_group;" ::: "memory")
#define CP_WAIT1()           asm volatile("cp.async.wait_group 1;" ::: "memory")
#define CP_WAIT0()           asm volatile("cp.async.wait_group 0;" ::: "memory")

// SMEM: double-buffered A hi/lo [128][72], B hi/lo [64][72] bf16
#define LDS  72
#define B_AH 0
#define B_AL (128 * LDS)
#define B_BH (2 * 128 * LDS)
#define B_BL (2 * 128 * LDS + 64 * LDS)
#define BUF_ELEMS (2 * 128 * LDS + 2 * 64 * LDS)     // 27648
#define SM_BYTES  (2 * BUF_ELEMS * 2)                // 110592 B

// ---------------------------------------------------------------------------
__device__ __forceinline__ void load_chunk_async(
    uint16_t* smb,
    const uint16_t* __restrict__ Ah, const uint16_t* __restrict__ Al,
    const uint16_t* __restrict__ Wh, const uint16_t* __restrict__ Wl,
    int Nc, int m0, int n0, int k0, int tid)
{
    // A: 2048 16B-chunks (hi then lo), 8 per thread
#pragma unroll
    for (int i = 0; i < 8; i++) {
        int idx = tid + i * 256;
        int mat = idx >> 10;
        int rem = idx & 1023;
        int row = rem >> 3;
        int kc  = (rem & 7) * 8;
        const uint16_t* src = (mat ? Al : Ah) + (size_t)(m0 + row) * KK + k0 + kc;
        uint32_t dst = smem_u32(smb + (mat ? B_AL : B_AH) + row * LDS + kc);
        CP_ASYNC16(dst, src);
    }
    // B: 1024 chunks, 4 per thread (row clamped; junk cols discarded in epilogue)
#pragma unroll
    for (int i = 0; i < 4; i++) {
        int idx = tid + i * 256;
        int mat = idx >> 9;
        int rem = idx & 511;
        int row = rem >> 3;
        int kc  = (rem & 7) * 8;
        int gr  = n0 + row; if (gr > Nc - 1) gr = Nc - 1;
        const uint16_t* src = (mat ? Wl : Wh) + (size_t)gr * KK + k0 + kc;
        uint32_t dst = smem_u32(smb + (mat ? B_BL : B_BH) + row * LDS + kc);
        CP_ASYNC16(dst, src);
    }
}

// C[m0:m0+128, n0:n0+64] = A @ W^T + bias. mode: 0 plain, 1 tanh*4, 2 kv-interleave
__device__ __forceinline__ void gemm_tile_mma(
    const uint16_t* __restrict__ Ah, const uint16_t* __restrict__ Al,
    const uint16_t* __restrict__ Wh, const uint16_t* __restrict__ Wl,
    const float* __restrict__ bias, float* __restrict__ C,
    int Nc, int ldC, int m0, int n0, int mode)
{
    extern __shared__ uint16_t sm[];
    const int tid = threadIdx.x;
    const int wid = tid >> 5, lane = tid & 31;
    const int wm = (wid & 3) * 32;
    const int wn = (wid >> 2) * 32;

    float acc[2][4][4];
#pragma unroll
    for (int mt = 0; mt < 2; mt++)
#pragma unroll
        for (int nt = 0; nt < 4; nt++)
#pragma unroll
            for (int i = 0; i < 4; i++) acc[mt][nt][i] = 0.f;

    const int a_r = lane & 15;
    const int a_c = (lane >> 4) * 8;
    const int b_r = lane & 7;
    const int b_c = ((lane >> 3) & 1) * 8;

    load_chunk_async(sm, Ah, Al, Wh, Wl, Nc, m0, n0, 0, tid);
    CP_COMMIT();

#pragma unroll 1
    for (int kc4 = 0; kc4 < 4; kc4++) {
        uint16_t* cur = sm + (kc4 & 1) * BUF_ELEMS;
        if (kc4 < 3) {
            load_chunk_async(sm + ((kc4 + 1) & 1) * BUF_ELEMS,
                             Ah, Al, Wh, Wl, Nc, m0, n0, (kc4 + 1) * 64, tid);
            CP_COMMIT();
            CP_WAIT1();
        } else {
            CP_WAIT0();
        }
        __syncthreads();

#pragma unroll
        for (int ks = 0; ks < 4; ks++) {
            const int kb = ks * 16;
            uint32_t ah[2][4], al[2][4];
#pragma unroll
            for (int mt = 0; mt < 2; mt++) {
                int row = wm + mt * 16 + a_r;
                ldsm_x4(ah[mt], smem_u32(cur + B_AH + row * LDS + kb + a_c));
                ldsm_x4(al[mt], smem_u32(cur + B_AL + row * LDS + kb + a_c));
            }
            uint32_t bh[4][2], bl[4][2];
#pragma unroll
            for (int nt = 0; nt < 4; nt++) {
                int row = wn + nt * 8 + b_r;
                ldsm_x2(bh[nt], smem_u32(cur + B_BH + row * LDS + kb + b_c));
                ldsm_x2(bl[nt], smem_u32(cur + B_BL + row * LDS + kb + b_c));
            }
#pragma unroll
            for (int mt = 0; mt < 2; mt++)
#pragma unroll
                for (int nt = 0; nt < 4; nt++) {
                    mma16816(acc[mt][nt], ah[mt], bh[nt]);
                    mma16816(acc[mt][nt], ah[mt], bl[nt]);
                    mma16816(acc[mt][nt], al[mt], bh[nt]);
                }
        }
        __syncthreads();
    }

    // ---- epilogue
    const int er = lane >> 2;
    const int ec = (lane & 3) * 2;
#pragma unroll
    for (int mt = 0; mt < 2; mt++) {
#pragma unroll
        for (int half = 0; half < 2; half++) {
            int gm = m0 + wm + mt * 16 + er + half * 8;
            float* crow = C + (size_t)gm * ldC;
#pragma unroll
            for (int nt = 0; nt < 4; nt++) {
                int gn = n0 + wn + nt * 8 + ec;
                if (gn < Nc) {
                    float v0 = acc[mt][nt][half * 2 + 0] + bias[gn];
                    float v1 = acc[mt][nt][half * 2 + 1] + bias[gn + 1];
                    if (mode == 1) { v0 = tanhf(v0) * 4.f; v1 = tanhf(v1) * 4.f; }
                    if (mode == 2) {
                        int c0 = (gn < 256)     ? gn * 2           : (gn - 256) * 2 + 1;
                        int c1 = (gn + 1 < 256) ? (gn + 1) * 2     : (gn + 1 - 256) * 2 + 1;
                        crow[c0] = v0;
                        crow[c1] = v1;
                    } else {
                        crow[gn]     = v0;
                        crow[gn + 1] = v1;
                    }
                }
            }
        }
    }
}

// in_gemm: blockIdx.x: 0-3 q | 4-6 off(tanh) | 7-14 kv(interleave)
__global__ __launch_bounds__(256)
void in_gemm_mma(const float* __restrict__ bq, const float* __restrict__ bo,
                 const float* __restrict__ bkv)
{
    const int t = blockIdx.x;
    const int m0 = blockIdx.y * 128;
    if (t < 4)
        gemm_tile_mma(g_xhi, g_xlo, g_wq_hi, g_wq_lo, bq, g_q, 256, 256, m0, t * 64, 0);
    else if (t < 7)
        gemm_tile_mma(g_xhi, g_xlo, g_wo_hi, g_wo_lo, bo, g_off, 144, 144, m0, (t - 4) * 64, 1);
    else
        gemm_tile_mma(g_xhi, g_xlo, g_wkv_hi, g_wkv_lo, bkv, g_kv, 512, 512, m0, (t - 7) * 64, 2);
}

__global__ __launch_bounds__(256)
void out_gemm_mma(const float* __restrict__ bout, float* __restrict__ C)
{
    gemm_tile_mma(g_ahi, g_alo, g_wu_hi, g_wu_lo, bout, C, 256, 256,
                  blockIdx.y * 128, blockIdx.x * 64, 0);
}

// ---------------------------------------------------------------------------
// fp32 -> bf16 hi/lo splits
// ---------------------------------------------------------------------------
__device__ __forceinline__ void split1(float v, uint16_t& h, uint16_t& l) {
    __nv_bfloat16 hb = __float2bfloat16(v);
    __nv_bfloat16 lb = __float2bfloat16(v - __bfloat162float(hb));
    h = __bfloat16_as_ushort(hb);
    l = __bfloat16_as_ushort(lb);
}

__global__ __launch_bounds__(256)
void split_x_kernel(const float* __restrict__ x) {
    int i4 = blockIdx.x * 256 + threadIdx.x;
    float4 v = ((const float4*)x)[i4];
    uint16_t h[4], l[4];
    split1(v.x, h[0], l[0]); split1(v.y, h[1], l[1]);
    split1(v.z, h[2], l[2]); split1(v.w, h[3], l[3]);
    ((uint64_t*)g_xhi)[i4] = *(const uint64_t*)h;
    ((uint64_t*)g_xlo)[i4] = *(const uint64_t*)l;
}

__global__ __launch_bounds__(256)
void split_w_kernel(const float* __restrict__ Wq, const float* __restrict__ Wo,
                    const float* __restrict__ Wkv, const float* __restrict__ Wu)
{
    int i = blockIdx.x * 256 + threadIdx.x;
    const float* src; uint16_t *hi, *lo; int off;
    if (i < 65536)        { src = Wq;  hi = g_wq_hi;  lo = g_wq_lo;  off = i; }
    else if (i < 102400)  { src = Wo;  hi = g_wo_hi;  lo = g_wo_lo;  off = i - 65536; }
    else if (i < 233472)  { src = Wkv; hi = g_wkv_hi; lo = g_wkv_lo; off = i - 102400; }
    else                  { src = Wu;  hi = g_wu_hi;  lo = g_wu_lo;  off = i - 233472; }
    split1(src[off], hi[off], lo[off]);
}

// ---------------------------------------------------------------------------
// Deformable attention: one warp per (b, h, n); lane = channel.
// kv interleaved: float2 {k, v} per channel. Outputs bf16 hi/lo.
// ---------------------------------------------------------------------------
__global__ __launch_bounds__(256)
void deform_attn_kernel()
{
    const int token = blockIdx.x;
    const int b = token / NTOK;
    const int n = token - b * NTOK;
    const int h = threadIdx.x >> 5;
    const int lane = threadIdx.x & 31;

    const float xbase = (float)(n % WIMG);
    const float ybase = (float)(n / WIMG);

    const float qc = g_q[(size_t)token * DM + h * HD + lane];
    const float2* offp = (const float2*)(g_off + (size_t)token * (HH * PP * 2) + h * PP * 2);
    // element stride per token row = 256 float2
    const float2* kvb = (const float2*)g_kv + (size_t)b * NTOK * 256 + h * HD + lane;

    float logits[PP], vs[PP];

#pragma unroll
    for (int p = 0; p < PP; p++) {
        float2 o = __ldg(&offp[p]);
        float sx = xbase + o.x;
        float sy = ybase + o.y;
        float x0f = floorf(sx), y0f = floorf(sy);
        int x0 = (int)x0f, y0 = (int)y0f;
        float wx1 = sx - x0f, wx0 = 1.f - wx1;
        float wy1 = sy - y0f, wy0 = 1.f - wy1;

        float kacc, vacc;
        if ((unsigned)x0 < (unsigned)(WIMG - 1) && (unsigned)y0 < (unsigned)(HIMG - 1)) {
            const float2* p00 = kvb + (size_t)(y0 * WIMG + x0) * 256;
            float w00 = wx0 * wy0, w10 = wx1 * wy0;
            float w01 = wx0 * wy1, w11 = wx1 * wy1;
            float2 c00 = p00[0];
            float2 c10 = p00[256];
            float2 c01 = p00[WIMG * 256];
            float2 c11 = p00[(WIMG + 1) * 256];
            kacc = w00 * c00.x + w10 * c10.x + w01 * c01.x + w11 * c11.x;
            vacc = w00 * c00.y + w10 * c10.y + w01 * c01.y + w11 * c11.y;
        } else {
            kacc = 0.f; vacc = 0.f;
#pragma unroll
            for (int cy = 0; cy < 2; cy++) {
                int yy = y0 + cy;
                if ((unsigned)yy >= (unsigned)HIMG) continue;
                float wy = cy ? wy1 : wy0;
#pragma unroll
                for (int cx = 0; cx < 2; cx++) {
                    int xx = x0 + cx;
                    if ((unsigned)xx >= (unsigned)WIMG) continue;
                    float wgt = (cx ? wx1 : wx0) * wy;
                    float2 c = kvb[(size_t)(yy * WIMG + xx) * 256];
                    kacc = fmaf(wgt, c.x, kacc);
                    vacc = fmaf(wgt, c.y, vacc);
                }
            }
        }
        float d = qc * kacc;
#pragma unroll
        for (int s = 16; s; s >>= 1) d += __shfl_xor_sync(0xffffffffu, d, s);
        logits[p] = d;
        vs[p] = vacc;
    }

    const float scale = 0.17677669529663687f;   // 1/sqrt(32)
    float sum = 0.f;
#pragma unroll
    for (int p = 0; p < PP; p++) { logits[p] = __expf(logits[p] * scale); sum += logits[p]; }
    float inv = 1.f / sum;
    float o = 0.f;
#pragma unroll
    for (int p = 0; p < PP; p++) o = fmaf(logits[p], vs[p], o);
    o *= inv;

    uint16_t hh, ll;
    split1(o, hh, ll);
    size_t oi = (size_t)token * DM + h * HD + lane;
    g_ahi[oi] = hh;
    g_alo[oi] = ll;
}

// ---------------------------------------------------------------------------
extern "C" void kernel_launch(void* const* d_in, const int* in_sizes, int n_in,
                              void* d_out, int out_size) {
    const float* x    = (const float*)d_in[0];
    const float* Wq   = (const float*)d_in[1];
    const float* bq   = (const float*)d_in[2];
    const float* Woff = (const float*)d_in[3];
    const float* boff = (const float*)d_in[4];
    const float* Wkv  = (const float*)d_in[5];
    const float* bkv  = (const float*)d_in[6];
    const float* Wout = (const float*)d_in[7];
    const float* bout = (const float*)d_in[8];
    float* out = (float*)d_out;

    static bool attr_done = false;
    if (!attr_done) {
        cudaFuncSetAttribute(in_gemm_mma,  cudaFuncAttributeMaxDynamicSharedMemorySize, SM_BYTES);
        cudaFuncSetAttribute(out_gemm_mma, cudaFuncAttributeMaxDynamicSharedMemorySize, SM_BYTES);
        attr_done = true;
    }

    split_x_kernel<<<(MROWS * KK / 4) / 256, 256>>>(x);
    split_w_kernel<<<299008 / 256, 256>>>(Wq, Woff, Wkv, Wout);

    in_gemm_mma<<<dim3(15, MROWS / 128), 256, SM_BYTES>>>(bq, boff, bkv);

    deform_attn_kernel<<<MROWS, 256>>>();

    out_gemm_mma<<<dim3(4, MROWS / 128), 256, SM_BYTES>>>(bout, out);
}